// round 6
// baseline (speedup 1.0000x reference)
#include <cuda_runtime.h>

#define NEG (-1e30f)
#define LOG2E 1.4426950408889634f
#define LN2   0.6931471805599453f

constexpr int B  = 8;
constexpr int T  = 200;
constexpr int U1 = 101;
constexpr int V  = 512;
constexpr int U  = U1 - 1;
constexpr int D  = T + U1 - 1;           // 300 anti-diagonals (d = 0..299)
constexpr int NCELL = B * T * U1;
constexpr int SB = 102;                  // padded row stride: lane stride ≡ 27 mod 32, conflict-free
constexpr int K  = 5;                    // diagonals per barrier (redundant-compute blocking)

// Padded log2-prob tables: [b][t*SB + u]  (pre-scaled by log2 e)
__device__ float g_blank[B * T * SB];
__device__ float g_emit [B * T * SB];
__device__ float g_loss [B];
__device__ int   g_ctr;

__device__ __forceinline__ float laddexp2(float a, float b) {
    float mx = fmaxf(a, b);
    float dd = -fabsf(a - b);
    return mx + __log2f(1.0f + exp2f(dd));
}

// One warp per (b,t,u) cell: logsumexp over V=512; dead cells skipped.
__global__ void __launch_bounds__(256) k_lse(const float* __restrict__ logits,
                                             const int*   __restrict__ targets,
                                             const int*   __restrict__ fbank_len,
                                             const int*   __restrict__ text_len) {
    int gw   = (blockIdx.x * blockDim.x + threadIdx.x) >> 5;
    int lane = threadIdx.x & 31;
    if (gw >= NCELL) return;

    int u = gw % U1;
    int t = (gw / U1) % T;
    int b = gw / (U1 * T);

    int lab_len = text_len[b] - 1;
    if (t >= fbank_len[b] || u > lab_len) return;   // never consumed by the DP

    const float4* p = reinterpret_cast<const float4*>(logits) + (size_t)gw * (V / 4);
    float4 v0 = p[lane];
    float4 v1 = p[lane + 32];
    float4 v2 = p[lane + 64];
    float4 v3 = p[lane + 96];

    float m = fmaxf(fmaxf(fmaxf(v0.x, v0.y), fmaxf(v0.z, v0.w)),
                    fmaxf(fmaxf(fmaxf(v1.x, v1.y), fmaxf(v1.z, v1.w)),
                          fmaxf(fmaxf(fmaxf(v2.x, v2.y), fmaxf(v2.z, v2.w)),
                                fmaxf(fmaxf(v3.x, v3.y), fmaxf(v3.z, v3.w)))));
#pragma unroll
    for (int o = 16; o; o >>= 1) m = fmaxf(m, __shfl_xor_sync(0xffffffffu, m, o));

    float s = __expf(v0.x - m) + __expf(v0.y - m) + __expf(v0.z - m) + __expf(v0.w - m)
            + __expf(v1.x - m) + __expf(v1.y - m) + __expf(v1.z - m) + __expf(v1.w - m)
            + __expf(v2.x - m) + __expf(v2.y - m) + __expf(v2.z - m) + __expf(v2.w - m)
            + __expf(v3.x - m) + __expf(v3.y - m) + __expf(v3.z - m) + __expf(v3.w - m);
#pragma unroll
    for (int o = 16; o; o >>= 1) s += __shfl_xor_sync(0xffffffffu, s, o);

    float lse = m + __logf(s);

    size_t base = (size_t)b * T * SB + t * SB + u;
    if (lane == 0) g_blank[base] = (v0.x - lse) * LOG2E;

    int lab = (u < U) ? targets[b * U1 + u + 1] : -1;
    if (lab >= 0) {
        int chunk = lab >> 2;
        if ((chunk & 31) == lane) {
            int j = chunk >> 5, c = lab & 3;
            float4 vv = (j == 0) ? v0 : (j == 1) ? v1 : (j == 2) ? v2 : v3;
            float ev  = (c == 0) ? vv.x : (c == 1) ? vv.y : (c == 2) ? vv.z : vv.w;
            g_emit[base] = (ev - lse) * LOG2E;
        }
    }
}

// Anti-diagonal alpha DP with K-diagonal blocking: 1 CTA / batch, 128 threads.
// Each superstep: read A[u-K..u], compute a K-deep triangle of cells redundantly
// in registers, write A[u], ONE barrier. 60 barriers total instead of 299.
constexpr int SMEM_DP = 2 * T * SB * (int)sizeof(float);

__global__ void __launch_bounds__(128) k_dp(const int* __restrict__ fbank_len,
                                            const int* __restrict__ text_len,
                                            float* __restrict__ out) {
    extern __shared__ float sm[];
    float* smb = sm;                     // blank [T][SB]
    float* sme = sm + T * SB;            // emit  [T][SB]
    __shared__ float A[2][128 + K];      // alpha row on base diagonal, double-buffered

    int b   = blockIdx.x;
    int tid = threadIdx.x;
    int u   = tid;

    // Stage tables (L2-resident, float4, padded layout matches gmem)
    {
        const float4* gb4 = reinterpret_cast<const float4*>(g_blank + (size_t)b * T * SB);
        const float4* ge4 = reinterpret_cast<const float4*>(g_emit  + (size_t)b * T * SB);
        float4* sb4 = reinterpret_cast<float4*>(smb);
        float4* se4 = reinterpret_cast<float4*>(sme);
        for (int i = tid; i < T * SB / 4; i += 128) { sb4[i] = gb4[i]; se4[i] = ge4[i]; }
    }

    if (tid < K) { A[0][tid] = NEG; A[1][tid] = NEG; }     // left padding
    A[0][u + K] = (u == 0) ? 0.0f : NEG;                   // diagonal d = 0

    int lab_len = text_len[b] - 1;
    int tfin    = fbank_len[b] - 1;
    int dfin    = tfin + lab_len;
    bool fin    = (u == lab_len);
    float afin  = NEG;
    __syncthreads();

    int buf = 0;
    for (int d0 = 0; d0 < D - 1; d0 += K) {
        float bb[K + 1];
#pragma unroll
        for (int j = 0; j <= K; ++j) bb[j] = A[buf][u - j + K];

#pragma unroll
        for (int i = 1; i <= K; ++i) {
            int d = d0 + i;
#pragma unroll
            for (int j = 0; j <= K - 1; ++j) {
                if (j <= K - i) {
                    int up = u - j;
                    int t  = d - up;
                    float nv = NEG;
                    if (up >= 0 && up < U1 && t >= 0 && t < T) {
                        float stay = (t  >= 1) ? bb[j]     + smb[(t - 1) * SB + up]  : NEG;
                        float mv   = (up >= 1) ? bb[j + 1] + sme[t * SB + (up - 1)]  : NEG;
                        nv = laddexp2(stay, mv);
                    }
                    bb[j] = nv;
                }
            }
            if (fin && d == dfin) afin = bb[0];
        }

        A[buf ^ 1][u + K] = bb[0];
        __syncthreads();
        buf ^= 1;
    }

    // Per-batch loss + fused mean via last-CTA reduction
    if (fin) {
        g_loss[b] = -LN2 * (afin + smb[tfin * SB + lab_len]);
        __threadfence();
        int done = atomicAdd(&g_ctr, 1);
        if (done == B - 1) {
            __threadfence();
            float s = 0.0f;
#pragma unroll
            for (int i = 0; i < B; ++i) s += *((volatile float*)&g_loss[i]);
            out[0] = s / (float)B;
            g_ctr = 0;                    // reset for next graph replay
        }
    }
}

extern "C" void kernel_launch(void* const* d_in, const int* in_sizes, int n_in,
                              void* d_out, int out_size) {
    const float* logits  = (const float*)d_in[0];
    const int*   targets = (const int*)d_in[1];
    const int*   fb      = (const int*)d_in[2];
    const int*   tl      = (const int*)d_in[3];

    cudaFuncSetAttribute(k_dp, cudaFuncAttributeMaxDynamicSharedMemorySize, SMEM_DP);

    int blocks = (NCELL * 32 + 255) / 256;  // one warp per cell
    k_lse<<<blocks, 256>>>(logits, targets, fb, tl);
    k_dp<<<B, 128, SMEM_DP>>>(fb, tl, (float*)d_out);
}

// round 7
// speedup vs baseline: 1.0475x; 1.0475x over previous
#include <cuda_runtime.h>

#define NEG (-1e30f)
#define LOG2E 1.4426950408889634f
#define LN2   0.6931471805599453f

constexpr int B  = 8;
constexpr int T  = 200;
constexpr int U1 = 101;
constexpr int V  = 512;
constexpr int U  = U1 - 1;
constexpr int D  = T + U1 - 1;           // 300 anti-diagonals (d = 0..299)
constexpr int NCELL = B * T * U1;
constexpr int SB = 102;                  // padded row stride: lane stride ≡ 27 mod 32, conflict-free
constexpr int K  = 5;                    // diagonals per barrier (redundant-compute blocking)

// Padded log2-prob tables: [b][t*SB + u]  (pre-scaled by log2 e)
__device__ float g_blank[B * T * SB];
__device__ float g_emit [B * T * SB];
__device__ float g_loss [B];
__device__ int   g_ctr;

// Raw MUFU ops (exp2f without fast-math is a slow libm path!)
__device__ __forceinline__ float ex2_(float x) {
    float r; asm("ex2.approx.ftz.f32 %0, %1;" : "=f"(r) : "f"(x)); return r;
}
__device__ __forceinline__ float lg2_(float x) {
    float r; asm("lg2.approx.ftz.f32 %0, %1;" : "=f"(r) : "f"(x)); return r;
}

__device__ __forceinline__ float laddexp2(float a, float b) {
    float mx = fmaxf(a, b);
    float dd = -fabsf(a - b);
    return mx + lg2_(1.0f + ex2_(dd));
}

// One warp per (b,t,u) cell: logsumexp over V=512; dead cells skipped.
__global__ void __launch_bounds__(256) k_lse(const float* __restrict__ logits,
                                             const int*   __restrict__ targets,
                                             const int*   __restrict__ fbank_len,
                                             const int*   __restrict__ text_len) {
    int gw   = (blockIdx.x * blockDim.x + threadIdx.x) >> 5;
    int lane = threadIdx.x & 31;
    if (gw >= NCELL) return;

    int u = gw % U1;
    int t = (gw / U1) % T;
    int b = gw / (U1 * T);

    int lab_len = text_len[b] - 1;
    if (t >= fbank_len[b] || u > lab_len) return;   // never consumed by the DP

    const float4* p = reinterpret_cast<const float4*>(logits) + (size_t)gw * (V / 4);
    float4 v0 = p[lane];
    float4 v1 = p[lane + 32];
    float4 v2 = p[lane + 64];
    float4 v3 = p[lane + 96];

    float m = fmaxf(fmaxf(fmaxf(v0.x, v0.y), fmaxf(v0.z, v0.w)),
                    fmaxf(fmaxf(fmaxf(v1.x, v1.y), fmaxf(v1.z, v1.w)),
                          fmaxf(fmaxf(fmaxf(v2.x, v2.y), fmaxf(v2.z, v2.w)),
                                fmaxf(fmaxf(v3.x, v3.y), fmaxf(v3.z, v3.w)))));
#pragma unroll
    for (int o = 16; o; o >>= 1) m = fmaxf(m, __shfl_xor_sync(0xffffffffu, m, o));

    float s = __expf(v0.x - m) + __expf(v0.y - m) + __expf(v0.z - m) + __expf(v0.w - m)
            + __expf(v1.x - m) + __expf(v1.y - m) + __expf(v1.z - m) + __expf(v1.w - m)
            + __expf(v2.x - m) + __expf(v2.y - m) + __expf(v2.z - m) + __expf(v2.w - m)
            + __expf(v3.x - m) + __expf(v3.y - m) + __expf(v3.z - m) + __expf(v3.w - m);
#pragma unroll
    for (int o = 16; o; o >>= 1) s += __shfl_xor_sync(0xffffffffu, s, o);

    float lse = m + __logf(s);

    size_t base = (size_t)b * T * SB + t * SB + u;
    if (lane == 0) g_blank[base] = (v0.x - lse) * LOG2E;

    int lab = (u < U) ? targets[b * U1 + u + 1] : -1;
    if (lab >= 0) {
        int chunk = lab >> 2;
        if ((chunk & 31) == lane) {
            int j = chunk >> 5, c = lab & 3;
            float4 vv = (j == 0) ? v0 : (j == 1) ? v1 : (j == 2) ? v2 : v3;
            float ev  = (c == 0) ? vv.x : (c == 1) ? vv.y : (c == 2) ? vv.z : vv.w;
            g_emit[base] = (ev - lse) * LOG2E;
        }
    }
}

// Anti-diagonal alpha DP with K-diagonal blocking: 1 CTA / batch, 128 threads.
// Each superstep: read A[u-K..u], compute a K-deep triangle of cells redundantly
// in registers, write A[u], ONE barrier. ~dfin/K barriers instead of 299.
constexpr int SMEM_DP = 2 * T * SB * (int)sizeof(float);

__global__ void __launch_bounds__(128) k_dp(const int* __restrict__ fbank_len,
                                            const int* __restrict__ text_len,
                                            float* __restrict__ out) {
    extern __shared__ float sm[];
    float* smb = sm;                     // blank [T][SB]
    float* sme = sm + T * SB;            // emit  [T][SB]
    __shared__ float A[2][128 + K];      // alpha row on base diagonal, double-buffered

    int b   = blockIdx.x;
    int tid = threadIdx.x;
    int u   = tid;

    // Stage tables (L2-resident, float4, padded layout matches gmem)
    {
        const float4* gb4 = reinterpret_cast<const float4*>(g_blank + (size_t)b * T * SB);
        const float4* ge4 = reinterpret_cast<const float4*>(g_emit  + (size_t)b * T * SB);
        float4* sb4 = reinterpret_cast<float4*>(smb);
        float4* se4 = reinterpret_cast<float4*>(sme);
        for (int i = tid; i < T * SB / 4; i += 128) { sb4[i] = gb4[i]; se4[i] = ge4[i]; }
    }

    if (tid < K) { A[0][tid] = NEG; A[1][tid] = NEG; }     // left padding
    A[0][u + K] = (u == 0) ? 0.0f : NEG;                   // diagonal d = 0

    int lab_len = text_len[b] - 1;
    int tfin    = fbank_len[b] - 1;
    int dfin    = tfin + lab_len;
    bool fin    = (u == lab_len);
    float afin  = NEG;
    __syncthreads();

    int buf = 0;
    for (int d0 = 0; d0 < dfin; d0 += K) {      // diagonals beyond dfin never consumed
        float bb[K + 1];
#pragma unroll
        for (int j = 0; j <= K; ++j) bb[j] = A[buf][u - j + K];

#pragma unroll
        for (int i = 1; i <= K; ++i) {
            int d = d0 + i;
#pragma unroll
            for (int j = 0; j <= K - 1; ++j) {
                if (j <= K - i) {
                    int up = u - j;
                    int t  = d - up;
                    float nv = NEG;
                    if (up >= 0 && up < U1 && t >= 0 && t < T) {
                        float stay = (t  >= 1) ? bb[j]     + smb[(t - 1) * SB + up]  : NEG;
                        float mv   = (up >= 1) ? bb[j + 1] + sme[t * SB + (up - 1)]  : NEG;
                        nv = laddexp2(stay, mv);
                    }
                    bb[j] = nv;
                }
            }
            if (fin && d == dfin) afin = bb[0];
        }

        A[buf ^ 1][u + K] = bb[0];
        __syncthreads();
        buf ^= 1;
    }

    // Per-batch loss + fused mean via last-CTA reduction
    if (fin) {
        g_loss[b] = -LN2 * (afin + smb[tfin * SB + lab_len]);
        __threadfence();
        int done = atomicAdd(&g_ctr, 1);
        if (done == B - 1) {
            __threadfence();
            float s = 0.0f;
#pragma unroll
            for (int i = 0; i < B; ++i) s += *((volatile float*)&g_loss[i]);
            out[0] = s / (float)B;
            g_ctr = 0;                    // reset for next graph replay
        }
    }
}

extern "C" void kernel_launch(void* const* d_in, const int* in_sizes, int n_in,
                              void* d_out, int out_size) {
    const float* logits  = (const float*)d_in[0];
    const int*   targets = (const int*)d_in[1];
    const int*   fb      = (const int*)d_in[2];
    const int*   tl      = (const int*)d_in[3];

    cudaFuncSetAttribute(k_dp, cudaFuncAttributeMaxDynamicSharedMemorySize, SMEM_DP);

    int blocks = (NCELL * 32 + 255) / 256;  // one warp per cell
    k_lse<<<blocks, 256>>>(logits, targets, fb, tl);
    k_dp<<<B, 128, SMEM_DP>>>(fb, tl, (float*)d_out);
}

// round 8
// speedup vs baseline: 1.7919x; 1.7106x over previous
#include <cuda_runtime.h>

#define NEG (-1e30f)
#define LOG2E 1.4426950408889634f
#define LN2   0.6931471805599453f

constexpr int B  = 8;
constexpr int T  = 200;
constexpr int U1 = 101;
constexpr int V  = 512;
constexpr int U  = U1 - 1;
constexpr int D  = T + U1 - 1;           // 300 anti-diagonals (d = 0..299)
constexpr int NCELL = B * T * U1;
constexpr int SB = 102;                  // padded row stride (conflict-free anti-diagonal reads)
constexpr int K  = 5;                    // diagonals per barrier
constexpr int NTRI = K * (K + 1) / 2;    // 15 triangle cells

// Padded log2-prob tables: [b][t*SB + u]  (pre-scaled by log2 e)
__device__ float g_blank[B * T * SB];
__device__ float g_emit [B * T * SB];
__device__ float g_loss [B];
__device__ int   g_ctr;

__device__ __forceinline__ float ex2_(float x) {
    float r; asm("ex2.approx.ftz.f32 %0, %1;" : "=f"(r) : "f"(x)); return r;
}
__device__ __forceinline__ float lg2_(float x) {
    float r; asm("lg2.approx.ftz.f32 %0, %1;" : "=f"(r) : "f"(x)); return r;
}
__device__ __forceinline__ float laddexp2(float a, float b) {
    float mx = fmaxf(a, b);
    float dd = -fabsf(a - b);
    return mx + lg2_(1.0f + ex2_(dd));
}

// One warp per (b,t,u) cell: logsumexp over V=512; dead cells skipped.
__global__ void __launch_bounds__(256) k_lse(const float* __restrict__ logits,
                                             const int*   __restrict__ targets,
                                             const int*   __restrict__ fbank_len,
                                             const int*   __restrict__ text_len) {
    int gw   = (blockIdx.x * blockDim.x + threadIdx.x) >> 5;
    int lane = threadIdx.x & 31;
    if (gw >= NCELL) return;

    int u = gw % U1;
    int t = (gw / U1) % T;
    int b = gw / (U1 * T);

    int lab_len = text_len[b] - 1;
    if (t >= fbank_len[b] || u > lab_len) return;   // never consumed by the DP

    const float4* p = reinterpret_cast<const float4*>(logits) + (size_t)gw * (V / 4);
    float4 v0 = p[lane];
    float4 v1 = p[lane + 32];
    float4 v2 = p[lane + 64];
    float4 v3 = p[lane + 96];

    float m = fmaxf(fmaxf(fmaxf(v0.x, v0.y), fmaxf(v0.z, v0.w)),
                    fmaxf(fmaxf(fmaxf(v1.x, v1.y), fmaxf(v1.z, v1.w)),
                          fmaxf(fmaxf(fmaxf(v2.x, v2.y), fmaxf(v2.z, v2.w)),
                                fmaxf(fmaxf(v3.x, v3.y), fmaxf(v3.z, v3.w)))));
#pragma unroll
    for (int o = 16; o; o >>= 1) m = fmaxf(m, __shfl_xor_sync(0xffffffffu, m, o));

    float s = __expf(v0.x - m) + __expf(v0.y - m) + __expf(v0.z - m) + __expf(v0.w - m)
            + __expf(v1.x - m) + __expf(v1.y - m) + __expf(v1.z - m) + __expf(v1.w - m)
            + __expf(v2.x - m) + __expf(v2.y - m) + __expf(v2.z - m) + __expf(v2.w - m)
            + __expf(v3.x - m) + __expf(v3.y - m) + __expf(v3.z - m) + __expf(v3.w - m);
#pragma unroll
    for (int o = 16; o; o >>= 1) s += __shfl_xor_sync(0xffffffffu, s, o);

    float lse = m + __logf(s);

    size_t base = (size_t)b * T * SB + t * SB + u;
    if (lane == 0) g_blank[base] = (v0.x - lse) * LOG2E;

    int lab = (u < U) ? targets[b * U1 + u + 1] : -1;
    if (lab >= 0) {
        int chunk = lab >> 2;
        if ((chunk & 31) == lane) {
            int j = chunk >> 5, c = lab & 3;
            float4 vv = (j == 0) ? v0 : (j == 1) ? v1 : (j == 2) ? v2 : v3;
            float ev  = (c == 0) ? vv.x : (c == 1) ? vv.y : (c == 2) ? vv.z : vv.w;
            g_emit[base] = (ev - lse) * LOG2E;
        }
    }
}

// K-diagonal-blocked alpha DP: 1 CTA / batch, 128 threads, 1 CTA/SM (max regs).
// Per superstep: hoist ALL table loads into registers, then run the pure-ALU
// logaddexp chain, then one barrier.
constexpr int SMEM_DP = 2 * T * SB * (int)sizeof(float);

__global__ void __launch_bounds__(128, 1) k_dp(const int* __restrict__ fbank_len,
                                               const int* __restrict__ text_len,
                                               float* __restrict__ out) {
    extern __shared__ float sm[];
    float* smb = sm;                     // blank [T][SB]
    float* sme = sm + T * SB;            // emit  [T][SB]
    __shared__ float A[2][128 + K];      // alpha on base diagonal, double-buffered

    int b   = blockIdx.x;
    int tid = threadIdx.x;
    int u   = tid;

    {   // Stage tables (L2-resident, float4, layout matches padded gmem)
        const float4* gb4 = reinterpret_cast<const float4*>(g_blank + (size_t)b * T * SB);
        const float4* ge4 = reinterpret_cast<const float4*>(g_emit  + (size_t)b * T * SB);
        float4* sb4 = reinterpret_cast<float4*>(smb);
        float4* se4 = reinterpret_cast<float4*>(sme);
        for (int i = tid; i < T * SB / 4; i += 128) { sb4[i] = gb4[i]; se4[i] = ge4[i]; }
    }

    if (tid < K) { A[0][tid] = NEG; A[1][tid] = NEG; }
    A[0][u + K] = (u == 0) ? 0.0f : NEG;

    int lab_len = text_len[b] - 1;
    int tfin    = fbank_len[b] - 1;
    int dfin    = tfin + lab_len;
    bool fin    = (u == lab_len);
    float afin  = NEG;
    __syncthreads();

    int buf = 0;
    for (int d0 = 0; d0 < dfin; d0 += K) {
        // ---- Phase 1: hoist alpha row + all triangle table values into regs ----
        float bb[K + 1];
#pragma unroll
        for (int j = 0; j <= K; ++j) bb[j] = A[buf][u - j + K];

        float tb[NTRI], te[NTRI];
        {
            int idx = 0;
#pragma unroll
            for (int i = 1; i <= K; ++i) {
#pragma unroll
                for (int j = 0; j <= K - i; ++j, ++idx) {
                    int up = u - j;
                    int t  = d0 + i - up;
                    bool vs = (t >= 1 && t < T && up >= 0 && up < U1);
                    bool vm = (t >= 0 && t < T && up >= 1 && up < U1);
                    tb[idx] = vs ? smb[(t - 1) * SB + up]   : NEG;
                    te[idx] = vm ? sme[t * SB + (up - 1)]   : NEG;
                }
            }
        }

        // ---- Phase 2: pure-register logaddexp chain ----
        {
            int idx = 0;
#pragma unroll
            for (int i = 1; i <= K; ++i) {
#pragma unroll
                for (int j = 0; j <= K - i; ++j, ++idx) {
                    float stay = bb[j]     + tb[idx];
                    float mv   = bb[j + 1] + te[idx];
                    bb[j] = laddexp2(stay, mv);
                }
                if (fin && (d0 + i) == dfin) afin = bb[0];
            }
        }

        A[buf ^ 1][u + K] = bb[0];
        __syncthreads();
        buf ^= 1;
    }

    // Per-batch loss + fused mean via last-CTA reduction
    if (fin) {
        g_loss[b] = -LN2 * (afin + smb[tfin * SB + lab_len]);
        __threadfence();
        int done = atomicAdd(&g_ctr, 1);
        if (done == B - 1) {
            __threadfence();
            float s = 0.0f;
#pragma unroll
            for (int i = 0; i < B; ++i) s += *((volatile float*)&g_loss[i]);
            out[0] = s / (float)B;
            g_ctr = 0;                    // reset for next graph replay
        }
    }
}

extern "C" void kernel_launch(void* const* d_in, const int* in_sizes, int n_in,
                              void* d_out, int out_size) {
    const float* logits  = (const float*)d_in[0];
    const int*   targets = (const int*)d_in[1];
    const int*   fb      = (const int*)d_in[2];
    const int*   tl      = (const int*)d_in[3];

    cudaFuncSetAttribute(k_dp, cudaFuncAttributeMaxDynamicSharedMemorySize, SMEM_DP);

    int blocks = (NCELL * 32 + 255) / 256;  // one warp per cell
    k_lse<<<blocks, 256>>>(logits, targets, fb, tl);
    k_dp<<<B, 128, SMEM_DP>>>(fb, tl, (float*)d_out);
}